// round 9
// baseline (speedup 1.0000x reference)
#include <cuda_runtime.h>
#include <cstdint>

// ---------------------------------------------------------------------------
// Problem constants
// ---------------------------------------------------------------------------
#define BB 1024      // batch
#define TT 512       // time steps
#define FF 64        // feature dim
#define HH 32        // latent dim
#define GG 128       // 4*HH gate width
#define MT (BB * TT) // total rows for phase A = 524288

// Scratch: gate pre-activations, split-half float2 layout.
//   xkp[((t*BB + b)*2 + p)*32 + l] : float2
//     p=0 -> (z[l],    z[32+l])  = (i_l, f_l)
//     p=1 -> (z[64+l], z[96+l])  = (g_l, o_l)
//  - scan warp (batch b, step t): two LDG.64, each 256B contiguous (nL=2)
//  - phase-A thread (row b,t) stores 32 consecutive float2 per pass (256B
//    per-thread contiguous; store scatter hides under fma-bound runtime)
// 64 * 524288 float2 = 256 MB (__device__ global: allocation-free rule)
__device__ float2 xkp_buf[(size_t)64 * MT];

// ---------------------------------------------------------------------------
// f32x2 packed helpers (sm_103a FFMA2 path — only reachable via PTX)
// ---------------------------------------------------------------------------
__device__ __forceinline__ unsigned long long pack2(float lo, float hi) {
    unsigned long long r;
    asm("mov.b64 %0, {%1, %2};" : "=l"(r) : "f"(lo), "f"(hi));
    return r;
}
__device__ __forceinline__ void unpack2(unsigned long long v, float& lo, float& hi) {
    asm("mov.b64 {%0, %1}, %2;" : "=f"(lo), "=f"(hi) : "l"(v));
}
__device__ __forceinline__ unsigned long long fma2(unsigned long long a,
                                                   unsigned long long b,
                                                   unsigned long long c) {
    unsigned long long d;
    asm("fma.rn.f32x2 %0, %1, %2, %3;" : "=l"(d) : "l"(a), "l"(b), "l"(c));
    return d;
}
__device__ __forceinline__ unsigned long long add2(unsigned long long a,
                                                   unsigned long long b) {
    unsigned long long d;
    asm("add.rn.f32x2 %0, %1, %2;" : "=l"(d) : "l"(a), "l"(b));
    return d;
}

// ---------------------------------------------------------------------------
// Fast nonlinearities: ex2.approx + rcp.approx -> abs err ~1e-7 per call,
// propagated output error ~1e-5..1e-4 << 1e-3 gate (audited round 6).
// Saturation-safe: ex2 under/overflow yields exact -1/+1 (tanh), 0/1 (sigmoid).
// ---------------------------------------------------------------------------
__device__ __forceinline__ float ex2f_(float x) {
    float y; asm("ex2.approx.f32 %0, %1;" : "=f"(y) : "f"(x)); return y;
}
__device__ __forceinline__ float rcpf_(float x) {
    float y; asm("rcp.approx.f32 %0, %1;" : "=f"(y) : "f"(x)); return y;
}
__device__ __forceinline__ float sigmoidf_(float x) {
    return rcpf_(1.0f + ex2f_(-1.4426950408889634f * x));
}
__device__ __forceinline__ float tanhf_(float x) {
    return 1.0f - 2.0f * rcpf_(1.0f + ex2f_(2.8853900817779268f * x));
}

// ---------------------------------------------------------------------------
// Phase A: fused  xk = tanh(x @ W_e + b_e) @ kernel + bias
//
// 256 threads/block, 1 row (b,t) per thread, r = blockIdx*256+tid.
// - x slice (64KB contiguous) staged coalesced into 65-padded shared;
//   per-thread row reads then bank-conflict-free ((tid+k)%32).
// - weights staged once as f32x2 pairs, read via LDS.128 broadcast.
// - enc round-trips through the padded shared region (kills the ea[] regs
//   before za[] comes alive).
// - phase 2 FISSIONED into two 32-accumulator passes (cols 0-63, 64-127),
//   each with its own bias+store epilogue: peak regs ~100 -> 2 blocks/SM
//   (smem 2x98KB <= 228KB carveout) -> 4 warps/SMSP fills the sync/MUFU/
//   staging bubbles of the partner block and halves the wave count.
// fma-pipe bound: 6144 FFMA2-instr/warp.
// ---------------------------------------------------------------------------
#define KA_THREADS 256
#define KA_SMEM_BYTES (4096 * 8 + 256 * 65 * 4 + 64 * 4 + 128 * 4)

__global__ __launch_bounds__(KA_THREADS, 2) void encode_gates_kernel(
    const float* __restrict__ x,
    const float* __restrict__ W_e,
    const float* __restrict__ b_e,
    const float* __restrict__ Wk,     // kernel [64][128]
    const float* __restrict__ bias)   // [128]
{
    extern __shared__ unsigned long long smem[];
    unsigned long long* shW = smem;                       // 4096 u64 (32KB)
    float* shRow  = (float*)(smem + 4096);                // [256][65] x, then enc
    float* shBE   = shRow + 256 * 65;                     // [64]
    float* shBias = shBE + 64;                            // [128]

    const int tid = threadIdx.x;
    const int r   = blockIdx.x * KA_THREADS + tid;        // row = b*TT + t

    // ---- stage W_e pairs (2048 u64) + b_e + x slice (16384 floats) ----
    const unsigned long long* We64 = (const unsigned long long*)W_e;
    for (int i = tid; i < 2048; i += KA_THREADS) shW[i] = We64[i];
    if (tid < 64) shBE[tid] = b_e[tid];
    {
        const float* xblk = x + (size_t)blockIdx.x * KA_THREADS * FF;
#pragma unroll 8
        for (int i = tid; i < 256 * 64; i += KA_THREADS) {
            int row = i >> 6, k = i & 63;
            shRow[row * 65 + k] = xblk[i];                // coalesced LDG
        }
    }
    __syncthreads();

    // ---- phase 1: enc accumulators, 32 f32x2 pairs ----
    float* myrow = shRow + tid * 65;
    {
        unsigned long long ea[32];
#pragma unroll
        for (int j = 0; j < 32; j++) ea[j] = 0ULL;

#pragma unroll 2
        for (int k = 0; k < FF; k++) {
            float xs = myrow[k];                          // conflict-free LDS
            unsigned long long xx = pack2(xs, xs);
            const ulonglong2* wrow = (const ulonglong2*)(shW + k * 32);
#pragma unroll
            for (int j2 = 0; j2 < 16; j2++) {
                ulonglong2 w = wrow[j2];                  // LDS.128 broadcast
                ea[2 * j2]     = fma2(xx, w.x, ea[2 * j2]);
                ea[2 * j2 + 1] = fma2(xx, w.y, ea[2 * j2 + 1]);
            }
        }
        __syncthreads();   // all x reads done before overwriting shRow

        // ---- tanh + bias, write own enc row back to padded shared ----
#pragma unroll
        for (int j = 0; j < 32; j++) {
            float a, b;
            unpack2(ea[j], a, b);
            myrow[2 * j]     = tanhf_(a + shBE[2 * j]);
            myrow[2 * j + 1] = tanhf_(b + shBE[2 * j + 1]);
        }
    }
    __syncthreads();   // enc visible; also done with shW(W_e)

    // ---- stage kernel pairs (4096 u64) + bias ----
    const unsigned long long* Wk64 = (const unsigned long long*)Wk;
    for (int i = tid; i < 4096; i += KA_THREADS) shW[i] = Wk64[i];
    if (tid < 128) shBias[tid] = bias[tid];
    __syncthreads();

    // ---- phase 2: two fissioned passes of 32 f32x2 accumulators ----
    const int b = r / TT;
    const int t = r % TT;
    float2* outbase = xkp_buf + ((size_t)t * BB + b) * 64;

#pragma unroll 1
    for (int p = 0; p < 2; p++) {
        unsigned long long za[32];                        // cols 64p .. 64p+63
#pragma unroll
        for (int j = 0; j < 32; j++) za[j] = 0ULL;

#pragma unroll 2
        for (int k = 0; k < FF; k++) {
            float ev = myrow[k];                          // conflict-free LDS
            unsigned long long ee = pack2(ev, ev);
            const ulonglong2* wrow = (const ulonglong2*)(shW + k * 64 + p * 32);
#pragma unroll
            for (int j2 = 0; j2 < 16; j2++) {
                ulonglong2 w = wrow[j2];                  // LDS.128 broadcast
                za[2 * j2]     = fma2(ee, w.x, za[2 * j2]);
                za[2 * j2 + 1] = fma2(ee, w.y, za[2 * j2 + 1]);
            }
        }

        // bias add for this half
        const float* bh = shBias + p * 64;
#pragma unroll
        for (int j = 0; j < 32; j++) {
            unsigned long long bz = *(const unsigned long long*)(bh + 2 * j);
            za[j] = add2(za[j], bz);
        }

        // store: out float2 l = (zc[l], zc[32+l]) where zc = cols 64p..64p+63.
        // zc[2j2]= za[j2].lo, zc[2j2+1]= za[j2].hi; zc[32+..] from za[16+j2].
        float2* outp = outbase + p * 32;                  // 256B contiguous
#pragma unroll
        for (int j2 = 0; j2 < 16; j2++) {
            float a0, a1, b0, b1;
            unpack2(za[j2],      a0, a1);                 // zc[2j2], zc[2j2+1]
            unpack2(za[16 + j2], b0, b1);                 // zc[32+2j2], zc[33+2j2]
            outp[2 * j2]     = make_float2(a0, b0);
            outp[2 * j2 + 1] = make_float2(a1, b1);
        }
    }
}

// ---------------------------------------------------------------------------
// Phase B+C: persistent LSTM scan, one warp per batch element.
// Lane l owns h[l], c[l] and gate pairs (i,f)+(g,o) as packed f32x2.
// R (rec_kernel) in 128 regs/lane; h broadcast via per-warp double-buffered
// shared ring of duplicated pairs (LDS.128 broadcast); xk via 4-deep register
// prefetch ring (2 x LDG.64/step, each 256B contiguous, nL=2; 8 outstanding
// < 55 cap, depth covers DRAM 577cyc at ~260cyc/step). Decode fused at end.
// 128 blocks x 8 warps -> 2 warps/SMSP; per-step fma-issue floor 256cyc/SMSP
// binds (chain latency ~195cyc hidden by 2-warp interleave).
// ---------------------------------------------------------------------------
__global__ __launch_bounds__(256, 1) void lstm_scan_kernel(
    const float* __restrict__ R,      // rec_kernel [32][128]
    const float* __restrict__ W_d,    // [32][1]
    const float* __restrict__ b_d,    // [1]
    float* __restrict__ out)          // [1024]
{
    __shared__ ulonglong2 shh[8][2][16];   // [warp][buf][16 x 2 dup-pairs]

    const int warp = threadIdx.x >> 5;
    const int lane = threadIdx.x & 31;
    const int b    = blockIdx.x * 8 + warp;   // grid = 128 -> 1024 warps

    // R pairs in registers: Rk[k][0] = (R[k][l], R[k][32+l]),
    //                       Rk[k][1] = (R[k][64+l], R[k][96+l])
    unsigned long long Rk[HH][2];
#pragma unroll
    for (int k = 0; k < HH; k++) {
        const float* row = R + k * GG;
        Rk[k][0] = pack2(row[lane],      row[32 + lane]);
        Rk[k][1] = pack2(row[64 + lane], row[96 + lane]);
    }

    float h = 0.0f, c = 0.0f;
    ((unsigned long long*)&shh[warp][0][0])[lane] = 0ULL;   // h_0 = 0
    __syncwarp();

    // xkp[((t*BB+b)*2 + p)*32 + lane]
    const float2* xk2 = xkp_buf + (size_t)b * 64 + lane;
    const size_t tstride = (size_t)BB * 64;
    float2 xif[4], xgo[4];
#pragma unroll
    for (int i = 0; i < 4; i++) {
        xif[i] = xk2[(size_t)i * tstride];
        xgo[i] = xk2[(size_t)i * tstride + 32];
    }

    for (int t0 = 0; t0 < TT; t0 += 4) {
#pragma unroll
        for (int u = 0; u < 4; u++) {
            const int t = t0 + u;
            float2 cif = xif[u], cgo = xgo[u];
            int tp = t + 4; if (tp > TT - 1) tp = TT - 1;  // clamped prefetch
            xif[u] = xk2[(size_t)tp * tstride];
            xgo[u] = xk2[(size_t)tp * tstride + 32];

            // 4 split accumulator chains (ILP 4 over FMA latency)
            unsigned long long a01a = pack2(cif.x, cif.y);   // (zi, zf)
            unsigned long long a23a = pack2(cgo.x, cgo.y);   // (zg, zo)
            unsigned long long a01b = 0ULL, a23b = 0ULL;

            const ulonglong2* hb = shh[warp][t & 1];
#pragma unroll
            for (int kk = 0; kk < 16; kk++) {
                ulonglong2 hh = hb[kk];                    // LDS.128 broadcast
                a01a = fma2(hh.x, Rk[2 * kk][0],     a01a);
                a23a = fma2(hh.x, Rk[2 * kk][1],     a23a);
                a01b = fma2(hh.y, Rk[2 * kk + 1][0], a01b);
                a23b = fma2(hh.y, Rk[2 * kk + 1][1], a23b);
            }
            unsigned long long a01 = add2(a01a, a01b);
            unsigned long long a23 = add2(a23a, a23b);

            float zi, zf, zg, zo;
            unpack2(a01, zi, zf);
            unpack2(a23, zg, zo);

            float ig = sigmoidf_(zi);
            float fg = sigmoidf_(zf);
            float gg = tanhf_(zg);
            float og = sigmoidf_(zo);
            c = fg * c + ig * gg;
            h = og * tanhf_(c);

            ((unsigned long long*)&shh[warp][(t + 1) & 1][0])[lane] = pack2(h, h);
            __syncwarp();
        }
    }

    // fused decode: out[b] = sigmoid(h_last . W_d + b_d)
    float v = h * W_d[lane];
#pragma unroll
    for (int s = 16; s > 0; s >>= 1)
        v += __shfl_xor_sync(0xffffffffu, v, s);
    if (lane == 0) out[b] = sigmoidf_(v + b_d[0]);
}

// ---------------------------------------------------------------------------
// launch
// ---------------------------------------------------------------------------
extern "C" void kernel_launch(void* const* d_in, const int* in_sizes, int n_in,
                              void* d_out, int out_size) {
    const float* x    = (const float*)d_in[0];   // [B,T,F]
    const float* W_e  = (const float*)d_in[1];   // [64,64]
    const float* b_e  = (const float*)d_in[2];   // [64]
    const float* Wk   = (const float*)d_in[3];   // [64,128]
    const float* rec  = (const float*)d_in[4];   // [32,128]
    const float* bias = (const float*)d_in[5];   // [128]
    const float* W_d  = (const float*)d_in[6];   // [32,1]
    const float* b_d  = (const float*)d_in[7];   // [1]
    float* out = (float*)d_out;

    (void)in_sizes; (void)n_in; (void)out_size;

    // Attribute set is not a stream op; legal under graph capture, idempotent.
    cudaFuncSetAttribute(encode_gates_kernel,
                         cudaFuncAttributeMaxDynamicSharedMemorySize,
                         KA_SMEM_BYTES);

    encode_gates_kernel<<<MT / KA_THREADS, KA_THREADS, KA_SMEM_BYTES>>>(
        x, W_e, b_e, Wk, bias);
    lstm_scan_kernel<<<BB / 8, 256>>>(rec, W_d, b_d, out);
}

// round 16
// speedup vs baseline: 1.2153x; 1.2153x over previous
#include <cuda_runtime.h>
#include <cstdint>

// ---------------------------------------------------------------------------
// Problem constants
// ---------------------------------------------------------------------------
#define BB 1024      // batch
#define TT 512       // time steps (power of 2: r>>9 / r&511)
#define FF 64        // feature dim
#define HH 32        // latent dim
#define GG 128       // 4*HH gate width
#define MT (BB * TT) // total rows for phase A = 524288

// Scratch: gate pre-activations, split-half float2 layout.
//   xkp[((t*BB + b)*2 + p)*32 + l] : float2
//     p=0 -> (z[l],    z[32+l])  = (i_l, f_l)
//     p=1 -> (z[64+l], z[96+l])  = (g_l, o_l)
// Scan warp (batch b, step t): two LDG.64, each 256B contiguous (nL=2).
// Phase-A stores go through shared-memory transpose staging so each
// warp-instruction writes 256B contiguous (nL=2) — round-9 ncu showed the
// old per-thread-contiguous stores cost 2048 L1 wavefronts/warp and bound
// the kernel.
__device__ float2 xkp_buf[(size_t)64 * MT];

// ---------------------------------------------------------------------------
// f32x2 packed helpers (sm_103a FFMA2 path — only reachable via PTX)
// ---------------------------------------------------------------------------
__device__ __forceinline__ unsigned long long pack2(float lo, float hi) {
    unsigned long long r;
    asm("mov.b64 %0, {%1, %2};" : "=l"(r) : "f"(lo), "f"(hi));
    return r;
}
__device__ __forceinline__ void unpack2(unsigned long long v, float& lo, float& hi) {
    asm("mov.b64 {%0, %1}, %2;" : "=f"(lo), "=f"(hi) : "l"(v));
}
__device__ __forceinline__ unsigned long long fma2(unsigned long long a,
                                                   unsigned long long b,
                                                   unsigned long long c) {
    unsigned long long d;
    asm("fma.rn.f32x2 %0, %1, %2, %3;" : "=l"(d) : "l"(a), "l"(b), "l"(c));
    return d;
}
__device__ __forceinline__ unsigned long long add2(unsigned long long a,
                                                   unsigned long long b) {
    unsigned long long d;
    asm("add.rn.f32x2 %0, %1, %2;" : "=l"(d) : "l"(a), "l"(b));
    return d;
}

// ---------------------------------------------------------------------------
// Fast nonlinearities: ex2.approx + rcp.approx (measured total rel_err 7e-8).
// ---------------------------------------------------------------------------
__device__ __forceinline__ float ex2f_(float x) {
    float y; asm("ex2.approx.f32 %0, %1;" : "=f"(y) : "f"(x)); return y;
}
__device__ __forceinline__ float rcpf_(float x) {
    float y; asm("rcp.approx.f32 %0, %1;" : "=f"(y) : "f"(x)); return y;
}
__device__ __forceinline__ float sigmoidf_(float x) {
    return rcpf_(1.0f + ex2f_(-1.4426950408889634f * x));
}
__device__ __forceinline__ float tanhf_(float x) {
    return 1.0f - 2.0f * rcpf_(1.0f + ex2f_(2.8853900817779268f * x));
}

// ---------------------------------------------------------------------------
// Phase A: fused  xk = tanh(x @ W_e + b_e) @ kernel + bias
// 256 threads/block, 1 row (b,t) per thread, r = blk*256+tid (t-fast).
// Smem (109,568 B/block, 2 blocks/SM = 219KB <= 228KB):
//   shW      [     0, 32768)  weights as f32x2 pairs (LDS.128 broadcast)
//   shRowF   [ 32768,100352)  float[256][66]: x slice -> enc -> pass1 staging
//   shBE     [100352,100608)
//   shBias   [100608,101120)
//   shStage0 [101120,109568)  float2[32][33] pass-0 store-transpose buffer
// Stores: per pass, z transposed through smem then warp-coalesced STG.64
// (256B contiguous per instruction). Store wavefronts/warp: 2048 -> ~64.
// ---------------------------------------------------------------------------
#define KA_THREADS 256
#define KA_SMEM_BYTES 109568

__device__ __forceinline__ void gemm_pass(unsigned long long* za,
                                          const float* myrow,
                                          const unsigned long long* shW,
                                          int p)
{
#pragma unroll
    for (int j = 0; j < 32; j++) za[j] = 0ULL;
#pragma unroll 2
    for (int k = 0; k < FF; k++) {
        float ev = myrow[k];
        unsigned long long ee = pack2(ev, ev);
        const ulonglong2* wrow = (const ulonglong2*)(shW + k * 64 + p * 32);
#pragma unroll
        for (int j2 = 0; j2 < 16; j2++) {
            ulonglong2 w = wrow[j2];                  // LDS.128 broadcast
            za[2 * j2]     = fma2(ee, w.x, za[2 * j2]);
            za[2 * j2 + 1] = fma2(ee, w.y, za[2 * j2 + 1]);
        }
    }
}

__global__ __launch_bounds__(KA_THREADS, 2) void encode_gates_kernel(
    const float* __restrict__ x,
    const float* __restrict__ W_e,
    const float* __restrict__ b_e,
    const float* __restrict__ Wk,     // kernel [64][128]
    const float* __restrict__ bias)   // [128]
{
    extern __shared__ unsigned long long smem[];
    unsigned long long* shW = smem;                        // 4096 u64
    float*  shRowF   = (float*)(smem + 4096);              // [256][66]
    float*  shBE     = shRowF + 256 * 66;                  // [64]
    float*  shBias   = shBE + 64;                          // [128]
    float2* shStage0 = (float2*)(shBias + 128);            // [32][33]

    const int tid   = threadIdx.x;
    const int w     = tid >> 5;
    const int lane  = tid & 31;
    const int rbase = blockIdx.x * KA_THREADS;

    // ---- stage W_e pairs + b_e + x slice (coalesced, 66-stride pad) ----
    const unsigned long long* We64 = (const unsigned long long*)W_e;
    for (int i = tid; i < 2048; i += KA_THREADS) shW[i] = We64[i];
    if (tid < 64) shBE[tid] = b_e[tid];
    {
        const float* xblk = x + (size_t)rbase * FF;
#pragma unroll 8
        for (int i = tid; i < 256 * 64; i += KA_THREADS) {
            int row = i >> 6, k = i & 63;
            shRowF[row * 66 + k] = xblk[i];               // coalesced LDG
        }
    }
    __syncthreads();

    // ---- phase 1: enc = tanh(x @ W_e + b_e), round-trip through shRowF ----
    float* myrow = shRowF + tid * 66;
    {
        unsigned long long ea[32];
#pragma unroll
        for (int j = 0; j < 32; j++) ea[j] = 0ULL;
#pragma unroll 2
        for (int k = 0; k < FF; k++) {
            float xs = myrow[k];
            unsigned long long xx = pack2(xs, xs);
            const ulonglong2* wrow = (const ulonglong2*)(shW + k * 32);
#pragma unroll
            for (int j2 = 0; j2 < 16; j2++) {
                ulonglong2 ww = wrow[j2];
                ea[2 * j2]     = fma2(xx, ww.x, ea[2 * j2]);
                ea[2 * j2 + 1] = fma2(xx, ww.y, ea[2 * j2 + 1]);
            }
        }
        __syncthreads();   // x reads done before overwriting shRowF
#pragma unroll
        for (int j = 0; j < 32; j++) {
            float a, b;
            unpack2(ea[j], a, b);
            myrow[2 * j]     = tanhf_(a + shBE[2 * j]);
            myrow[2 * j + 1] = tanhf_(b + shBE[2 * j + 1]);
        }
    }
    __syncthreads();

    // ---- stage kernel pairs + bias ----
    const unsigned long long* Wk64 = (const unsigned long long*)Wk;
    for (int i = tid; i < 4096; i += KA_THREADS) shW[i] = Wk64[i];
    if (tid < 128) shBias[tid] = bias[tid];
    __syncthreads();

    // ================= pass 0: cols 0..63 -> p=0 half =================
    {
        unsigned long long za[32];
        gemm_pass(za, myrow, shW, 0);
#pragma unroll
        for (int j = 0; j < 32; j++) {
            unsigned long long bz = *(const unsigned long long*)(shBias + 2 * j);
            za[j] = add2(za[j], bz);
        }
        // 8 rounds: warp q transposes its 32 rows through shStage0,
        // then ALL warps store 32 rows coalesced (4 rows/warp, nL=2).
        for (int q = 0; q < 8; q++) {
            __syncthreads();                 // buffer free from prev round
            if (w == q) {
#pragma unroll
                for (int j2 = 0; j2 < 16; j2++) {
                    float a0, a1, b0, b1;
                    unpack2(za[j2],      a0, a1);
                    unpack2(za[16 + j2], b0, b1);
                    shStage0[lane * 33 + 2 * j2]     = make_float2(a0, b0);
                    shStage0[lane * 33 + 2 * j2 + 1] = make_float2(a1, b1);
                }
            }
            __syncthreads();
#pragma unroll
            for (int i = 0; i < 4; i++) {
                int rl = w * 4 + i;                       // 0..31 in round
                int rr = rbase + q * 32 + rl;
                int bb = rr >> 9, t = rr & 511;           // TT = 512
                xkp_buf[((size_t)t * BB + bb) * 64 + lane] =
                    shStage0[rl * 33 + lane];             // 256B contiguous
            }
        }
    }

    // ================= pass 1: cols 64..127 -> p=1 half =================
    {
        unsigned long long za[32];
        gemm_pass(za, myrow, shW, 1);
#pragma unroll
        for (int j = 0; j < 32; j++) {
            unsigned long long bz = *(const unsigned long long*)(shBias + 64 + 2 * j);
            za[j] = add2(za[j], bz);
        }
        __syncthreads();                 // all enc reads done; shRowF now free
        float2* stg = (float2*)shRowF;   // [256][33] float2 = 67,584B fits
#pragma unroll
        for (int j2 = 0; j2 < 16; j2++) {
            float a0, a1, b0, b1;
            unpack2(za[j2],      a0, a1);
            unpack2(za[16 + j2], b0, b1);
            stg[tid * 33 + 2 * j2]     = make_float2(a0, b0);
            stg[tid * 33 + 2 * j2 + 1] = make_float2(a1, b1);
        }
        __syncthreads();
#pragma unroll 4
        for (int i = 0; i < 32; i++) {
            int rl = w * 32 + i;
            int rr = rbase + rl;
            int bb = rr >> 9, t = rr & 511;
            xkp_buf[((size_t)t * BB + bb) * 64 + 32 + lane] =
                stg[rl * 33 + lane];                      // 256B contiguous
        }
    }
}

// ---------------------------------------------------------------------------
// Phase B+C: persistent LSTM scan, one warp per batch element.
// Round-9 ncu: latency-bound (fma 31.6%, ~900 cyc/step). Fixes:
//  - h broadcast via __shfl_sync (h stays in registers) — removes the
//    STS -> __syncwarp -> LDS round trip from the serial path entirely.
//  - 8 accumulator chains of depth 8 (was 4 x depth 16): GEMM chain 64->32.
// No shared memory, no barriers. xk via 4-deep LDG.64 prefetch ring.
// ---------------------------------------------------------------------------
__global__ __launch_bounds__(256) void lstm_scan_kernel(
    const float* __restrict__ R,      // rec_kernel [32][128]
    const float* __restrict__ W_d,    // [32][1]
    const float* __restrict__ b_d,    // [1]
    float* __restrict__ out)          // [1024]
{
    const int lane = threadIdx.x & 31;
    const int b    = blockIdx.x * 8 + (threadIdx.x >> 5); // 128 blocks x 8 warps

    // R pairs in registers: Rk[k][0] = (R[k][l], R[k][32+l]),
    //                       Rk[k][1] = (R[k][64+l], R[k][96+l])
    unsigned long long Rk[HH][2];
#pragma unroll
    for (int k = 0; k < HH; k++) {
        const float* row = R + k * GG;
        Rk[k][0] = pack2(row[lane],      row[32 + lane]);
        Rk[k][1] = pack2(row[64 + lane], row[96 + lane]);
    }

    float h = 0.0f, c = 0.0f;   // lane l owns h_l, c_l

    // xkp[((t*BB+b)*2 + p)*32 + lane]
    const float2* xk2 = xkp_buf + (size_t)b * 64 + lane;
    const size_t tstride = (size_t)BB * 64;
    float2 xif[4], xgo[4];
#pragma unroll
    for (int i = 0; i < 4; i++) {
        xif[i] = xk2[(size_t)i * tstride];
        xgo[i] = xk2[(size_t)i * tstride + 32];
    }

    for (int t0 = 0; t0 < TT; t0 += 4) {
#pragma unroll
        for (int u = 0; u < 4; u++) {
            const int t = t0 + u;
            float2 cif = xif[u], cgo = xgo[u];
            int tp = t + 4; if (tp > TT - 1) tp = TT - 1;  // clamped prefetch
            xif[u] = xk2[(size_t)tp * tstride];
            xgo[u] = xk2[(size_t)tp * tstride + 32];

            // 8 chains of depth 8 over k=0..31, h broadcast via shfl
            unsigned long long A0 = pack2(cif.x, cif.y), A1 = 0, A2 = 0, A3 = 0;
            unsigned long long B0 = pack2(cgo.x, cgo.y), B1 = 0, B2 = 0, B3 = 0;
#pragma unroll
            for (int k = 0; k < 32; k += 4) {
                float h0 = __shfl_sync(0xffffffffu, h, k);
                float h1 = __shfl_sync(0xffffffffu, h, k + 1);
                float h2 = __shfl_sync(0xffffffffu, h, k + 2);
                float h3 = __shfl_sync(0xffffffffu, h, k + 3);
                unsigned long long hh0 = pack2(h0, h0);
                unsigned long long hh1 = pack2(h1, h1);
                unsigned long long hh2 = pack2(h2, h2);
                unsigned long long hh3 = pack2(h3, h3);
                A0 = fma2(hh0, Rk[k][0],     A0);
                B0 = fma2(hh0, Rk[k][1],     B0);
                A1 = fma2(hh1, Rk[k + 1][0], A1);
                B1 = fma2(hh1, Rk[k + 1][1], B1);
                A2 = fma2(hh2, Rk[k + 2][0], A2);
                B2 = fma2(hh2, Rk[k + 2][1], B2);
                A3 = fma2(hh3, Rk[k + 3][0], A3);
                B3 = fma2(hh3, Rk[k + 3][1], B3);
            }
            unsigned long long a01 = add2(add2(A0, A1), add2(A2, A3));
            unsigned long long a23 = add2(add2(B0, B1), add2(B2, B3));

            float zi, zf, zg, zo;
            unpack2(a01, zi, zf);
            unpack2(a23, zg, zo);

            float ig = sigmoidf_(zi);
            float fg = sigmoidf_(zf);
            float gg = tanhf_(zg);
            float og = sigmoidf_(zo);
            c = fg * c + ig * gg;
            h = og * tanhf_(c);
        }
    }

    // fused decode: out[b] = sigmoid(h_last . W_d + b_d)
    float v = h * W_d[lane];
#pragma unroll
    for (int s = 16; s > 0; s >>= 1)
        v += __shfl_xor_sync(0xffffffffu, v, s);
    if (lane == 0) out[b] = sigmoidf_(v + b_d[0]);
}

// ---------------------------------------------------------------------------
// launch
// ---------------------------------------------------------------------------
extern "C" void kernel_launch(void* const* d_in, const int* in_sizes, int n_in,
                              void* d_out, int out_size) {
    const float* x    = (const float*)d_in[0];   // [B,T,F]
    const float* W_e  = (const float*)d_in[1];   // [64,64]
    const float* b_e  = (const float*)d_in[2];   // [64]
    const float* Wk   = (const float*)d_in[3];   // [64,128]
    const float* rec  = (const float*)d_in[4];   // [32,128]
    const float* bias = (const float*)d_in[5];   // [128]
    const float* W_d  = (const float*)d_in[6];   // [32,1]
    const float* b_d  = (const float*)d_in[7];   // [1]
    float* out = (float*)d_out;

    (void)in_sizes; (void)n_in; (void)out_size;

    // Attribute set is not a stream op; legal under graph capture, idempotent.
    cudaFuncSetAttribute(encode_gates_kernel,
                         cudaFuncAttributeMaxDynamicSharedMemorySize,
                         KA_SMEM_BYTES);

    encode_gates_kernel<<<MT / KA_THREADS, KA_THREADS, KA_SMEM_BYTES>>>(
        x, W_e, b_e, Wk, bias);
    lstm_scan_kernel<<<BB / 8, 256>>>(rec, W_d, b_d, out);
}